// round 2
// baseline (speedup 1.0000x reference)
#include <cuda_runtime.h>
#include <stdint.h>

// EmbeddingDropout: out[b,s,:] = W[words[b,s],:] * keep[words[b,s]]
// keep[v] from JAX threefry2x32 in *partitionable* mode (default since JAX 0.5):
//   per flat index i: (o0,o1) = threefry2x32(key=(0,42), x0=hi32(i)=0, x1=lo32(i)=i)
//   bits = o0 ^ o1 ; u = bitcast((bits>>9)|0x3f800000)-1 ; keep = (u>=0.1)/0.9

#define V_VOCAB 50257
#define D_EMB   1024

__device__ float d_keep[V_VOCAB];

__device__ __forceinline__ uint32_t rotl32(uint32_t v, int d) {
    return (v << d) | (v >> (32 - d));
}

__device__ __forceinline__ void threefry2x32_k42(uint32_t x0, uint32_t x1,
                                                 uint32_t& o0, uint32_t& o1) {
    // key = (0, 42): ks0 = 0, ks1 = 42, ks2 = 0 ^ 42 ^ 0x1BD11BDA
    const uint32_t ks0 = 0u;
    const uint32_t ks1 = 42u;
    const uint32_t ks2 = 42u ^ 0x1BD11BDAu;

    x0 += ks0; x1 += ks1;
#define TF_ROUND(r) { x0 += x1; x1 = rotl32(x1, (r)); x1 ^= x0; }
    TF_ROUND(13) TF_ROUND(15) TF_ROUND(26) TF_ROUND(6)
    x0 += ks1; x1 += ks2 + 1u;
    TF_ROUND(17) TF_ROUND(29) TF_ROUND(16) TF_ROUND(24)
    x0 += ks2; x1 += ks0 + 2u;
    TF_ROUND(13) TF_ROUND(15) TF_ROUND(26) TF_ROUND(6)
    x0 += ks0; x1 += ks1 + 3u;
    TF_ROUND(17) TF_ROUND(29) TF_ROUND(16) TF_ROUND(24)
    x0 += ks1; x1 += ks2 + 4u;
    TF_ROUND(13) TF_ROUND(15) TF_ROUND(26) TF_ROUND(6)
    x0 += ks2; x1 += ks0 + 5u;
#undef TF_ROUND
    o0 = x0; o1 = x1;
}

__global__ void mask_kernel() {
    int i = blockIdx.x * blockDim.x + threadIdx.x;
    if (i >= V_VOCAB) return;
    // Partitionable threefry: counter = 64-bit flat index, split hi/lo.
    // i < 2^32 -> x0 (hi) = 0, x1 (lo) = i. 32-bit bits = o0 ^ o1.
    uint32_t o0, o1;
    threefry2x32_k42(0u, (uint32_t)i, o0, o1);
    uint32_t bits = o0 ^ o1;
    float u = __uint_as_float((bits >> 9) | 0x3f800000u) - 1.0f;
    d_keep[i] = (u >= 0.1f) ? (1.0f / 0.9f) : 0.0f;
}

__global__ void gather_kernel(const int* __restrict__ words,
                              const float* __restrict__ W,
                              float* __restrict__ out) {
    int tok = blockIdx.x;
    int row = __ldg(&words[tok]);
    float k = d_keep[row];
    const float4* __restrict__ src =
        reinterpret_cast<const float4*>(W + (size_t)row * D_EMB);
    float4* __restrict__ dst =
        reinterpret_cast<float4*>(out + (size_t)tok * D_EMB);
    float4 v = src[threadIdx.x];
    v.x *= k; v.y *= k; v.z *= k; v.w *= k;
    dst[threadIdx.x] = v;
}

extern "C" void kernel_launch(void* const* d_in, const int* in_sizes, int n_in,
                              void* d_out, int out_size) {
    const int*   words = (const int*)d_in[0];   // [32, 2048] int32
    const float* W     = (const float*)d_in[1]; // [50257, 1024] f32
    float*       out   = (float*)d_out;         // [32, 2048, 1024] f32

    int n_tokens = in_sizes[0];                 // 65536

    mask_kernel<<<(V_VOCAB + 255) / 256, 256>>>();
    gather_kernel<<<n_tokens, D_EMB / 4>>>(words, W, out);
}

// round 3
// speedup vs baseline: 1.2588x; 1.2588x over previous
#include <cuda_runtime.h>
#include <stdint.h>

// EmbeddingDropout, fused single kernel:
// out[tok,:] = W[words[tok],:] * keep(words[tok])
// keep(v) via JAX partitionable threefry2x32, key=(0,42):
//   (o0,o1) = threefry2x32(x0=0, x1=v); bits = o0^o1
//   u = bitcast((bits>>9)|0x3f800000)-1 ; keep = (u>=0.1) ? 1/0.9 : 0

#define D_EMB 1024

__device__ __forceinline__ uint32_t rotl32(uint32_t v, int d) {
    return (v << d) | (v >> (32 - d));
}

__device__ __forceinline__ float keep_of_row(uint32_t x1) {
    const uint32_t ks1 = 42u;
    const uint32_t ks2 = 42u ^ 0x1BD11BDAu;
    uint32_t x0 = 0u;
    x1 += ks1;
#define TF_ROUND(r) { x0 += x1; x1 = rotl32(x1, (r)); x1 ^= x0; }
    TF_ROUND(13) TF_ROUND(15) TF_ROUND(26) TF_ROUND(6)
    x0 += ks1; x1 += ks2 + 1u;
    TF_ROUND(17) TF_ROUND(29) TF_ROUND(16) TF_ROUND(24)
    x0 += ks2; x1 += 0u + 2u;
    TF_ROUND(13) TF_ROUND(15) TF_ROUND(26) TF_ROUND(6)
    x0 += 0u; x1 += ks1 + 3u;
    TF_ROUND(17) TF_ROUND(29) TF_ROUND(16) TF_ROUND(24)
    x0 += ks1; x1 += ks2 + 4u;
    TF_ROUND(13) TF_ROUND(15) TF_ROUND(26) TF_ROUND(6)
    x0 += ks2; x1 += 0u + 5u;
#undef TF_ROUND
    uint32_t bits = x0 ^ x1;
    float u = __uint_as_float((bits >> 9) | 0x3f800000u) - 1.0f;
    return (u >= 0.1f) ? (1.0f / 0.9f) : 0.0f;
}

// One warp per token: lane l handles float4 elements l, l+32, ..., l+224
// (8 independent 16B loads in flight per thread).
__global__ void gather_kernel(const int* __restrict__ words,
                              const float* __restrict__ W,
                              float* __restrict__ out,
                              int n_tokens) {
    int warp_id = (blockIdx.x * blockDim.x + threadIdx.x) >> 5;
    int lane = threadIdx.x & 31;
    if (warp_id >= n_tokens) return;

    int row = __ldg(&words[warp_id]);
    float k = keep_of_row((uint32_t)row);

    const float4* __restrict__ src =
        reinterpret_cast<const float4*>(W + (size_t)row * D_EMB);
    float4* __restrict__ dst =
        reinterpret_cast<float4*>(out + (size_t)warp_id * D_EMB);

    float4 v[8];
#pragma unroll
    for (int j = 0; j < 8; j++)
        v[j] = src[lane + 32 * j];
#pragma unroll
    for (int j = 0; j < 8; j++) {
        v[j].x *= k; v[j].y *= k; v[j].z *= k; v[j].w *= k;
        __stcs(&dst[lane + 32 * j], v[j]);   // streaming store: don't pollute L2
    }
}

extern "C" void kernel_launch(void* const* d_in, const int* in_sizes, int n_in,
                              void* d_out, int out_size) {
    const int*   words = (const int*)d_in[0];   // [32, 2048] int32
    const float* W     = (const float*)d_in[1]; // [50257, 1024] f32
    float*       out   = (float*)d_out;         // [32, 2048, 1024] f32

    int n_tokens = in_sizes[0];                 // 65536
    // 8 warps (= 8 tokens) per 256-thread block
    int blocks = (n_tokens + 7) / 8;
    gather_kernel<<<blocks, 256>>>(words, W, out, n_tokens);
}